// round 14
// baseline (speedup 1.0000x reference)
#include <cuda_runtime.h>
#include <cuda_fp16.h>
#include <math.h>
#include <stdint.h>

#define E 8
#define D 1024
#define NMAX 4096
#define CAP 4096

#define BM 128
#define BN 256
#define KCH 64                 // halfs of K per stage
#define NSTAGE (D / KCH)       // 16
#define NRING 4
#define ROWPAD 72              // halfs per smem row (144B)
#define ROWBYTES (KCH * 2)     // 128B payload per row per stage
#define STG_BYTES ((BM + BN) * ROWPAD * 2)     // 55296
#define TX_BYTES  ((BM + BN) * ROWBYTES)       // 49152 per stage
#define SMEM_BYTES (NRING * STG_BYTES)         // 221184

#define MT_TILES (NMAX / BM)       // 32
#define NT_TILES (D / BN)          // 4
#define TILES_PER_PASS (MT_TILES * E * NT_TILES)   // 1024
#define TOTAL_TILES (2 * TILES_PER_PASS)           // 2048

// ---------------- scratch (device globals; no runtime allocation) ----------------
__device__ __half g_Hh[(size_t)E * CAP * D];
__device__ __half g_xh[(size_t)NMAX * D];
__device__ __half g_W1h[(size_t)E * D * D];
__device__ __half g_W2h[(size_t)E * D * D];
__device__ int    g_cnt[E];
__device__ int    g_tok[E * CAP];
__device__ float  g_wslot[E * CAP];       // routing weight per bucket slot
__device__ int    g_tile_ctr;
__device__ int    g_ready[E * MT_TILES];

// ---------------- helpers ----------------
__device__ __forceinline__ uint32_t smem_u32(const void* p) {
    uint32_t a;
    asm("{ .reg .u64 t; cvta.to.shared.u64 t, %1; cvt.u32.u64 %0, t; }" : "=r"(a) : "l"(p));
    return a;
}
__device__ __forceinline__ void bulk_cp(uint32_t dst, const void* src, uint32_t bytes, uint32_t mbar) {
    asm volatile(
        "cp.async.bulk.shared::cta.global.mbarrier::complete_tx::bytes [%0], [%1], %2, [%3];"
        :: "r"(dst), "l"(src), "r"(bytes), "r"(mbar) : "memory");
}
__device__ __forceinline__ void mbar_init(uint32_t mbar, uint32_t count) {
    asm volatile("mbarrier.init.shared.b64 [%0], %1;" :: "r"(mbar), "r"(count) : "memory");
}
__device__ __forceinline__ void mbar_expect_tx(uint32_t mbar, uint32_t bytes) {
    asm volatile("mbarrier.arrive.expect_tx.shared.b64 _, [%0], %1;" :: "r"(mbar), "r"(bytes) : "memory");
}
__device__ __forceinline__ void mbar_wait(uint32_t mbar, uint32_t parity) {
    uint32_t done;
    asm volatile(
        "{\n\t.reg .pred p;\n\t"
        "mbarrier.try_wait.parity.shared.b64 p, [%1], %2;\n\t"
        "selp.b32 %0, 1, 0, p;\n\t}"
        : "=r"(done) : "r"(mbar), "r"(parity) : "memory");
    if (!done) {
        asm volatile(
            "{\n\t.reg .pred P1;\n\t"
            "WL_%=:\n\t"
            "mbarrier.try_wait.parity.shared.b64 P1, [%0], %1, 0x989680;\n\t"
            "@P1 bra.uni WD_%=;\n\t"
            "bra.uni WL_%=;\n\t"
            "WD_%=:\n\t}"
            :: "r"(mbar), "r"(parity) : "memory");
    }
}
__device__ __forceinline__ void ldsm4(uint32_t& r0, uint32_t& r1, uint32_t& r2, uint32_t& r3,
                                      uint32_t addr) {
    asm volatile("ldmatrix.sync.aligned.m8n8.x4.shared.b16 {%0,%1,%2,%3}, [%4];"
                 : "=r"(r0), "=r"(r1), "=r"(r2), "=r"(r3) : "r"(addr));
}
__device__ __forceinline__ void mma_f16(float* c, const uint32_t* a, uint32_t b0, uint32_t b1) {
    asm volatile(
        "mma.sync.aligned.m16n8k16.row.col.f32.f16.f16.f32 "
        "{%0,%1,%2,%3}, {%4,%5,%6,%7}, {%8,%9}, {%0,%1,%2,%3};"
        : "+f"(c[0]), "+f"(c[1]), "+f"(c[2]), "+f"(c[3])
        : "r"(a[0]), "r"(a[1]), "r"(a[2]), "r"(a[3]), "r"(b0), "r"(b1));
}

__global__ void zero_counts_kernel() {
    if (threadIdx.x < E) g_cnt[threadIdx.x] = 0;
    if (threadIdx.x == 0) g_tile_ctr = 0;
    for (int i = threadIdx.x; i < E * MT_TILES; i += 32) g_ready[i] = 0;
}

// ---------------- convert weights to fp16 ----------------
__global__ void convert_w_kernel(const float* __restrict__ w1,
                                 const float* __restrict__ w2)
{
    size_t n = (size_t)E * D * D / 4;
    size_t i = (size_t)blockIdx.x * blockDim.x + threadIdx.x;
    size_t stride = (size_t)gridDim.x * blockDim.x;
    for (; i < n; i += stride) {
        float4 v1 = ((const float4*)w1)[i];
        __half2* o1 = (__half2*)g_W1h + i * 2;
        o1[0] = __floats2half2_rn(v1.x, v1.y);
        o1[1] = __floats2half2_rn(v1.z, v1.w);
        float4 v2 = ((const float4*)w2)[i];
        __half2* o2 = (__half2*)g_W2h + i * 2;
        o2[0] = __floats2half2_rn(v2.x, v2.y);
        o2[1] = __floats2half2_rn(v2.z, v2.w);
    }
}

// ---------------- gating (emits fp16 x, zeros y) ----------------
__global__ void gate_kernel(const float* __restrict__ x,
                            const float* __restrict__ gW,
                            const float* __restrict__ gb,
                            float* __restrict__ gate_prob_out,
                            float* __restrict__ y,
                            int N)
{
    int token = blockIdx.x;
    if (token >= N) return;

    __shared__ float sx[D];
    __shared__ float slog[E];

    const float* xr = x + (size_t)token * D;
    __half* xout = g_xh + (size_t)token * D;
    float4* yz = (float4*)(y + (size_t)token * D);
    for (int i = threadIdx.x; i < D; i += blockDim.x) {
        float v = xr[i];
        sx[i] = v;
        xout[i] = __float2half_rn(v);
    }
    for (int i = threadIdx.x; i < D / 4; i += blockDim.x)
        yz[i] = make_float4(0.f, 0.f, 0.f, 0.f);
    __syncthreads();

    int w = threadIdx.x >> 5, lane = threadIdx.x & 31;
    float s = 0.f;
    const float* wr = gW + w * D;
    for (int k = lane; k < D; k += 32) s += sx[k] * wr[k];
    #pragma unroll
    for (int o = 16; o; o >>= 1) s += __shfl_xor_sync(0xffffffffu, s, o);
    if (lane == 0) slog[w] = s + gb[w];
    __syncthreads();

    if (threadIdx.x == 0) {
        float p[E];
        float mx = -1e30f;
        #pragma unroll
        for (int e = 0; e < E; e++) mx = fmaxf(mx, slog[e]);
        float sum = 0.f;
        #pragma unroll
        for (int e = 0; e < E; e++) { p[e] = expf(slog[e] - mx); sum += p[e]; }
        float inv = 1.f / sum;

        int i0 = 0; float p0 = -1.f;
        #pragma unroll
        for (int e = 0; e < E; e++) {
            p[e] *= inv;
            gate_prob_out[(size_t)token * E + e] = p[e];
            if (p[e] > p0) { p0 = p[e]; i0 = e; }
        }
        int i1 = -1; float p1 = -1.f;
        #pragma unroll
        for (int e = 0; e < E; e++)
            if (e != i0 && p[e] > p1) { p1 = p[e]; i1 = e; }

        float e1 = expf(p1 - p0);
        float w0 = 1.f / (1.f + e1);
        float w1 = e1 / (1.f + e1);

        int pos0 = atomicAdd(&g_cnt[i0], 1);
        int pos1 = atomicAdd(&g_cnt[i1], 1);
        g_tok[i0 * CAP + pos0] = token;
        g_tok[i1 * CAP + pos1] = token;
        g_wslot[i0 * CAP + pos0] = w0;
        g_wslot[i1 * CAP + pos1] = w1;
    }
}

// ---------------- persistent fused two-pass expert GEMM ----------------
// Tile queue: ids [0, 1024) = pass 1, [1024, 2048) = pass 2.
// Pass 1 -> g_Hh (relu+b1). Pass 2 -> atomicAdd into y (w * (acc+b2)).
__global__ __launch_bounds__(512, 1)
void expert_gemm_persistent(const float* __restrict__ b1,
                            const float* __restrict__ b2,
                            float* __restrict__ y)
{
    extern __shared__ char sm[];
    __shared__ uint64_t mbar_store[NRING];
    __shared__ int s_tile;
    uint32_t smb  = smem_u32(sm);
    uint32_t mbar = smem_u32(mbar_store);

    int tid = threadIdx.x;   // 0..511
    int wid = tid >> 5, lane = tid & 31;
    int g  = lane >> 2, tg = lane & 3;
    int wm = (wid >> 2) * 32;       // 4 warps in m (32 rows each)
    int wn = (wid & 3) * 64;        // 4 warps in n (64 cols each)

    if (tid == 0)
        #pragma unroll
        for (int b = 0; b < NRING; b++) mbar_init(mbar + b * 8, 1);
    __syncthreads();

    // ldmatrix offsets (bytes within a stage) — tile-independent
    uint32_t a_off[2], b_off[4];
    #pragma unroll
    for (int mt = 0; mt < 2; mt++) {
        int row = wm + mt * 16 + (lane & 15);
        a_off[mt] = (uint32_t)(row * ROWPAD + (lane >> 4) * 8) * 2u;
    }
    #pragma unroll
    for (int nt2 = 0; nt2 < 4; nt2++) {
        int row = wn + nt2 * 16 + (lane & 7) + ((lane >> 4) & 1) * 8;
        b_off[nt2] = (uint32_t)((BM + row) * ROWPAD + ((lane >> 3) & 1) * 8) * 2u;
    }

    bool is_loader = (tid < BM + BN);
    uint32_t r_sm = smb + (uint32_t)tid * (ROWPAD * 2);

    int ph[NRING] = {0, 0, 0, 0};   // phases persist across tiles

    for (;;) {
        if (tid == 0) s_tile = atomicAdd(&g_tile_ctr, 1);
        __syncthreads();
        int t = s_tile;
        __syncthreads();
        if (t >= TOTAL_TILES) break;

        int mode = (t >= TILES_PER_PASS) ? 1 : 0;
        int idx  = mode ? (t - TILES_PER_PASS) : t;
        int mt_i = idx >> 5;
        int e    = (idx & 31) >> 2;
        int nt_i = idx & 3;
        int ne   = g_cnt[e];
        int m0   = mt_i * BM;
        int n0   = nt_i * BN;
        if (m0 >= ne) continue;

        // pass-2: wait for this (e, m-tile) to be fully produced by pass-1
        if (mode == 1) {
            if (tid == 0) {
                const int* rp = &g_ready[e * MT_TILES + mt_i];
                int v;
                do {
                    asm volatile("ld.global.cg.s32 %0, [%1];" : "=r"(v) : "l"(rp) : "memory");
                } while (v < NT_TILES);
            }
            __syncthreads();
        }

        // per-tile loader pointer
        const __half* Rptr = nullptr;
        if (tid < BM) {
            if (mode == 0) {
                int tok = (m0 + tid < ne) ? g_tok[e * CAP + m0 + tid] : 0;
                Rptr = g_xh + (size_t)tok * D;
            } else {
                Rptr = g_Hh + ((size_t)e * CAP + m0 + tid) * D;
            }
        } else if (is_loader) {
            const __half* W = (mode == 0) ? g_W1h : g_W2h;
            Rptr = W + ((size_t)e * D + n0 + (tid - BM)) * D;
        }

        // prologue: stages 0..2 into buffers 0..2
        if (tid == 0) {
            mbar_expect_tx(mbar + 0, TX_BYTES);
            mbar_expect_tx(mbar + 8, TX_BYTES);
            mbar_expect_tx(mbar + 16, TX_BYTES);
        }
        __syncthreads();
        if (is_loader) {
            bulk_cp(r_sm,                 Rptr,           ROWBYTES, mbar);
            bulk_cp(r_sm + STG_BYTES,     Rptr + KCH,     ROWBYTES, mbar + 8);
            bulk_cp(r_sm + 2 * STG_BYTES, Rptr + 2 * KCH, ROWBYTES, mbar + 16);
        }

        float acc[2][8][4];
        #pragma unroll
        for (int mt = 0; mt < 2; mt++)
            #pragma unroll
            for (int nt = 0; nt < 8; nt++)
                #pragma unroll
                for (int i = 0; i < 4; i++) acc[mt][nt][i] = 0.f;

        #pragma unroll 1
        for (int s = 0; s < NSTAGE; s++) {
            int b = s & (NRING - 1);
            mbar_wait(mbar + b * 8, ph[b]);
            ph[b] ^= 1;
            __syncthreads();               // all warps done with buffer (s-1)&3

            if (s + 3 < NSTAGE) {
                int nb = (s + 3) & (NRING - 1);   // == (s-1)&3: just-freed buffer
                if (tid == 0) mbar_expect_tx(mbar + nb * 8, TX_BYTES);
                if (is_loader)
                    bulk_cp(r_sm + (uint32_t)nb * STG_BYTES, Rptr + (s + 3) * KCH,
                            ROWBYTES, mbar + nb * 8);
            }

            uint32_t stg = smb + (uint32_t)b * STG_BYTES;

            #pragma unroll
            for (int kk = 0; kk < KCH / 16; kk++) {
                uint32_t koff = (uint32_t)kk * 32u;
                uint32_t a[2][4], bfr[4][4];
                #pragma unroll
                for (int mt = 0; mt < 2; mt++)
                    ldsm4(a[mt][0], a[mt][1], a[mt][2], a[mt][3], stg + a_off[mt] + koff);
                #pragma unroll
                for (int nt2 = 0; nt2 < 4; nt2++)
                    ldsm4(bfr[nt2][0], bfr[nt2][1], bfr[nt2][2], bfr[nt2][3], stg + b_off[nt2] + koff);
                #pragma unroll
                for (int mt = 0; mt < 2; mt++)
                    #pragma unroll
                    for (int nt = 0; nt < 8; nt++)
                        mma_f16(acc[mt][nt], a[mt], bfr[nt >> 1][(nt & 1) * 2], bfr[nt >> 1][(nt & 1) * 2 + 1]);
            }
        }

        // ---------------- epilogue ----------------
        if (mode == 0) {
            const float* brw = b1 + (size_t)e * D + n0;
            #pragma unroll
            for (int mt = 0; mt < 2; mt++) {
                #pragma unroll
                for (int rr = 0; rr < 2; rr++) {
                    int m = m0 + wm + mt * 16 + rr * 8 + g;
                    if (m >= ne) continue;
                    size_t rowbase = ((size_t)e * CAP + m) * D + n0;
                    #pragma unroll
                    for (int nt = 0; nt < 8; nt++) {
                        int col = wn + nt * 8 + tg * 2;
                        float v0 = fmaxf(acc[mt][nt][rr * 2 + 0] + brw[col], 0.f);
                        float v1 = fmaxf(acc[mt][nt][rr * 2 + 1] + brw[col + 1], 0.f);
                        *(__half2*)(g_Hh + rowbase + col) = __floats2half2_rn(v0, v1);
                    }
                }
            }
            __threadfence();
            __syncthreads();
            if (tid == 0) atomicAdd(&g_ready[e * MT_TILES + mt_i], 1);
        } else {
            const float* brw = b2 + (size_t)e * D + n0;
            #pragma unroll
            for (int mt = 0; mt < 2; mt++) {
                #pragma unroll
                for (int rr = 0; rr < 2; rr++) {
                    int m = m0 + wm + mt * 16 + rr * 8 + g;
                    if (m >= ne) continue;
                    int   tok = g_tok[e * CAP + m];
                    float wgt = g_wslot[e * CAP + m];
                    float* yrow = y + (size_t)tok * D + n0;
                    #pragma unroll
                    for (int nt = 0; nt < 8; nt++) {
                        int col = wn + nt * 8 + tg * 2;
                        atomicAdd(yrow + col,     wgt * (acc[mt][nt][rr * 2 + 0] + brw[col]));
                        atomicAdd(yrow + col + 1, wgt * (acc[mt][nt][rr * 2 + 1] + brw[col + 1]));
                    }
                }
            }
        }
    }
}

extern "C" void kernel_launch(void* const* d_in, const int* in_sizes, int n_in,
                              void* d_out, int out_size)
{
    const float* x  = (const float*)d_in[0];
    const float* gW = (const float*)d_in[1];
    const float* gb = (const float*)d_in[2];
    const float* w1 = (const float*)d_in[3];
    const float* b1 = (const float*)d_in[4];
    const float* w2 = (const float*)d_in[5];
    const float* b2 = (const float*)d_in[6];

    int N = in_sizes[0] / D;   // 4096

    float* y         = (float*)d_out;
    float* gate_prob = (float*)d_out + (size_t)N * D;

    static int sm_count = 0;
    if (!sm_count) {
        cudaDeviceGetAttribute(&sm_count, cudaDevAttrMultiProcessorCount, 0);
        if (sm_count <= 0) sm_count = 148;
        cudaFuncSetAttribute(expert_gemm_persistent,
                             cudaFuncAttributeMaxDynamicSharedMemorySize, SMEM_BYTES);
    }

    zero_counts_kernel<<<1, 32>>>();
    convert_w_kernel<<<1184, 256>>>(w1, w2);
    gate_kernel<<<N, 256>>>(x, gW, gb, gate_prob, y, N);

    expert_gemm_persistent<<<sm_count, 512, SMEM_BYTES>>>(b1, b2, y);
}

// round 15
// speedup vs baseline: 1.1704x; 1.1704x over previous
#include <cuda_runtime.h>
#include <cuda_fp16.h>
#include <math.h>
#include <stdint.h>

#define E 8
#define D 1024
#define NMAX 4096
#define CAP 4096

#define BM 128
#define BN 256
#define KCH 64                 // halfs of K per stage
#define NSTAGE (D / KCH)       // 16
#define NRING 4
#define ROWPAD 72              // halfs per smem row (144B)
#define ROWBYTES (KCH * 2)     // 128B payload per row per stage
#define STG_BYTES ((BM + BN) * ROWPAD * 2)     // 55296
#define TX_BYTES  ((BM + BN) * ROWBYTES)       // 49152 per stage
#define SMEM_BYTES (NRING * STG_BYTES)         // 221184

#define MT_TILES (NMAX / BM)       // 32
#define NT_TILES (D / BN)          // 4
#define TILES_PER_PASS (MT_TILES * E * NT_TILES)   // 1024
#define TOTAL_TILES (2 * TILES_PER_PASS)           // 2048

// ---------------- scratch (device globals; no runtime allocation) ----------------
__device__ __half g_Hh[(size_t)E * CAP * D];
__device__ float  g_O[(size_t)E * CAP * D];
__device__ __half g_xh[(size_t)NMAX * D];
__device__ __half g_W1h[(size_t)E * D * D];
__device__ __half g_W2h[(size_t)E * D * D];
__device__ int    g_cnt[E];
__device__ int    g_tok[E * CAP];
__device__ int    g_slot[NMAX * 2];
__device__ float  g_wgt[NMAX * 2];
__device__ int    g_tile_ctr;
__device__ int    g_ready[E * MT_TILES];

// ---------------- helpers ----------------
__device__ __forceinline__ uint32_t smem_u32(const void* p) {
    uint32_t a;
    asm("{ .reg .u64 t; cvta.to.shared.u64 t, %1; cvt.u32.u64 %0, t; }" : "=r"(a) : "l"(p));
    return a;
}
__device__ __forceinline__ void bulk_cp(uint32_t dst, const void* src, uint32_t bytes, uint32_t mbar) {
    asm volatile(
        "cp.async.bulk.shared::cta.global.mbarrier::complete_tx::bytes [%0], [%1], %2, [%3];"
        :: "r"(dst), "l"(src), "r"(bytes), "r"(mbar) : "memory");
}
__device__ __forceinline__ void mbar_init(uint32_t mbar, uint32_t count) {
    asm volatile("mbarrier.init.shared.b64 [%0], %1;" :: "r"(mbar), "r"(count) : "memory");
}
__device__ __forceinline__ void mbar_expect_tx(uint32_t mbar, uint32_t bytes) {
    asm volatile("mbarrier.arrive.expect_tx.shared.b64 _, [%0], %1;" :: "r"(mbar), "r"(bytes) : "memory");
}
__device__ __forceinline__ void mbar_wait(uint32_t mbar, uint32_t parity) {
    uint32_t done;
    asm volatile(
        "{\n\t.reg .pred p;\n\t"
        "mbarrier.try_wait.parity.shared.b64 p, [%1], %2;\n\t"
        "selp.b32 %0, 1, 0, p;\n\t}"
        : "=r"(done) : "r"(mbar), "r"(parity) : "memory");
    if (!done) {
        asm volatile(
            "{\n\t.reg .pred P1;\n\t"
            "WL_%=:\n\t"
            "mbarrier.try_wait.parity.shared.b64 P1, [%0], %1, 0x989680;\n\t"
            "@P1 bra.uni WD_%=;\n\t"
            "bra.uni WL_%=;\n\t"
            "WD_%=:\n\t}"
            :: "r"(mbar), "r"(parity) : "memory");
    }
}
__device__ __forceinline__ void ldsm4(uint32_t& r0, uint32_t& r1, uint32_t& r2, uint32_t& r3,
                                      uint32_t addr) {
    asm volatile("ldmatrix.sync.aligned.m8n8.x4.shared.b16 {%0,%1,%2,%3}, [%4];"
                 : "=r"(r0), "=r"(r1), "=r"(r2), "=r"(r3) : "r"(addr));
}
__device__ __forceinline__ void mma_f16(float* c, const uint32_t* a, uint32_t b0, uint32_t b1) {
    asm volatile(
        "mma.sync.aligned.m16n8k16.row.col.f32.f16.f16.f32 "
        "{%0,%1,%2,%3}, {%4,%5,%6,%7}, {%8,%9}, {%0,%1,%2,%3};"
        : "+f"(c[0]), "+f"(c[1]), "+f"(c[2]), "+f"(c[3])
        : "r"(a[0]), "r"(a[1]), "r"(a[2]), "r"(a[3]), "r"(b0), "r"(b1));
}

__global__ void zero_counts_kernel() {
    if (threadIdx.x < E) g_cnt[threadIdx.x] = 0;
    if (threadIdx.x == 0) g_tile_ctr = 0;
    for (int i = threadIdx.x; i < E * MT_TILES; i += 32) g_ready[i] = 0;
}

// ---------------- convert weights to fp16 ----------------
__global__ void convert_w_kernel(const float* __restrict__ w1,
                                 const float* __restrict__ w2)
{
    size_t n = (size_t)E * D * D / 4;
    size_t i = (size_t)blockIdx.x * blockDim.x + threadIdx.x;
    size_t stride = (size_t)gridDim.x * blockDim.x;
    for (; i < n; i += stride) {
        float4 v1 = ((const float4*)w1)[i];
        __half2* o1 = (__half2*)g_W1h + i * 2;
        o1[0] = __floats2half2_rn(v1.x, v1.y);
        o1[1] = __floats2half2_rn(v1.z, v1.w);
        float4 v2 = ((const float4*)w2)[i];
        __half2* o2 = (__half2*)g_W2h + i * 2;
        o2[0] = __floats2half2_rn(v2.x, v2.y);
        o2[1] = __floats2half2_rn(v2.z, v2.w);
    }
}

// ---------------- gating (emits fp16 x) ----------------
__global__ void gate_kernel(const float* __restrict__ x,
                            const float* __restrict__ gW,
                            const float* __restrict__ gb,
                            float* __restrict__ gate_prob_out,
                            int N)
{
    int token = blockIdx.x;
    if (token >= N) return;

    __shared__ float sx[D];
    __shared__ float slog[E];

    const float* xr = x + (size_t)token * D;
    __half* xout = g_xh + (size_t)token * D;
    for (int i = threadIdx.x; i < D; i += blockDim.x) {
        float v = xr[i];
        sx[i] = v;
        xout[i] = __float2half_rn(v);
    }
    __syncthreads();

    int w = threadIdx.x >> 5, lane = threadIdx.x & 31;
    float s = 0.f;
    const float* wr = gW + w * D;
    for (int k = lane; k < D; k += 32) s += sx[k] * wr[k];
    #pragma unroll
    for (int o = 16; o; o >>= 1) s += __shfl_xor_sync(0xffffffffu, s, o);
    if (lane == 0) slog[w] = s + gb[w];
    __syncthreads();

    if (threadIdx.x == 0) {
        float p[E];
        float mx = -1e30f;
        #pragma unroll
        for (int e = 0; e < E; e++) mx = fmaxf(mx, slog[e]);
        float sum = 0.f;
        #pragma unroll
        for (int e = 0; e < E; e++) { p[e] = expf(slog[e] - mx); sum += p[e]; }
        float inv = 1.f / sum;

        int i0 = 0; float p0 = -1.f;
        #pragma unroll
        for (int e = 0; e < E; e++) {
            p[e] *= inv;
            gate_prob_out[(size_t)token * E + e] = p[e];
            if (p[e] > p0) { p0 = p[e]; i0 = e; }
        }
        int i1 = -1; float p1 = -1.f;
        #pragma unroll
        for (int e = 0; e < E; e++)
            if (e != i0 && p[e] > p1) { p1 = p[e]; i1 = e; }

        float e1 = expf(p1 - p0);
        float w0 = 1.f / (1.f + e1);
        float w1 = e1 / (1.f + e1);

        int pos0 = atomicAdd(&g_cnt[i0], 1);
        int pos1 = atomicAdd(&g_cnt[i1], 1);
        g_tok[i0 * CAP + pos0] = token;
        g_tok[i1 * CAP + pos1] = token;
        g_slot[token * 2 + 0] = i0 * CAP + pos0;
        g_slot[token * 2 + 1] = i1 * CAP + pos1;
        g_wgt[token * 2 + 0] = w0;
        g_wgt[token * 2 + 1] = w1;
    }
}

// ---------------- persistent fused two-pass expert GEMM (4-stage ring) ----------------
// Tile queue: ids [0, 1024) = pass 1, [1024, 2048) = pass 2.
// Pass 1 -> g_Hh (relu+b1). Pass 2 -> g_O (b2). Separate combine kernel.
__global__ __launch_bounds__(512, 1)
void expert_gemm_persistent(const float* __restrict__ b1,
                            const float* __restrict__ b2)
{
    extern __shared__ char sm[];
    __shared__ uint64_t mbar_store[NRING];
    __shared__ int s_tile;
    uint32_t smb  = smem_u32(sm);
    uint32_t mbar = smem_u32(mbar_store);

    int tid = threadIdx.x;   // 0..511
    int wid = tid >> 5, lane = tid & 31;
    int g  = lane >> 2, tg = lane & 3;
    int wm = (wid >> 2) * 32;       // 4 warps in m (32 rows each)
    int wn = (wid & 3) * 64;        // 4 warps in n (64 cols each)

    if (tid == 0)
        #pragma unroll
        for (int b = 0; b < NRING; b++) mbar_init(mbar + b * 8, 1);
    __syncthreads();

    // ldmatrix offsets (bytes within a stage) — tile-independent
    uint32_t a_off[2], b_off[4];
    #pragma unroll
    for (int mt = 0; mt < 2; mt++) {
        int row = wm + mt * 16 + (lane & 15);
        a_off[mt] = (uint32_t)(row * ROWPAD + (lane >> 4) * 8) * 2u;
    }
    #pragma unroll
    for (int nt2 = 0; nt2 < 4; nt2++) {
        int row = wn + nt2 * 16 + (lane & 7) + ((lane >> 4) & 1) * 8;
        b_off[nt2] = (uint32_t)((BM + row) * ROWPAD + ((lane >> 3) & 1) * 8) * 2u;
    }

    bool is_loader = (tid < BM + BN);
    uint32_t r_sm = smb + (uint32_t)tid * (ROWPAD * 2);

    int ph[NRING] = {0, 0, 0, 0};   // phases persist across tiles

    for (;;) {
        if (tid == 0) s_tile = atomicAdd(&g_tile_ctr, 1);
        __syncthreads();
        int t = s_tile;
        __syncthreads();
        if (t >= TOTAL_TILES) break;

        int mode = (t >= TILES_PER_PASS) ? 1 : 0;
        int idx  = mode ? (t - TILES_PER_PASS) : t;
        int mt_i = idx >> 5;
        int e    = (idx & 31) >> 2;
        int nt_i = idx & 3;
        int ne   = g_cnt[e];
        int m0   = mt_i * BM;
        int n0   = nt_i * BN;
        if (m0 >= ne) continue;

        // pass-2: wait for this (e, m-tile) to be fully produced by pass-1
        if (mode == 1) {
            if (tid == 0) {
                const int* rp = &g_ready[e * MT_TILES + mt_i];
                int v;
                do {
                    asm volatile("ld.global.cg.s32 %0, [%1];" : "=r"(v) : "l"(rp) : "memory");
                } while (v < NT_TILES);
            }
            __syncthreads();
        }

        // per-tile loader pointer
        const __half* Rptr = nullptr;
        if (tid < BM) {
            if (mode == 0) {
                int tok = (m0 + tid < ne) ? g_tok[e * CAP + m0 + tid] : 0;
                Rptr = g_xh + (size_t)tok * D;
            } else {
                Rptr = g_Hh + ((size_t)e * CAP + m0 + tid) * D;
            }
        } else if (is_loader) {
            const __half* W = (mode == 0) ? g_W1h : g_W2h;
            Rptr = W + ((size_t)e * D + n0 + (tid - BM)) * D;
        }

        // prologue: stages 0..2 into buffers 0..2
        if (tid == 0) {
            mbar_expect_tx(mbar + 0, TX_BYTES);
            mbar_expect_tx(mbar + 8, TX_BYTES);
            mbar_expect_tx(mbar + 16, TX_BYTES);
        }
        __syncthreads();
        if (is_loader) {
            bulk_cp(r_sm,                 Rptr,           ROWBYTES, mbar);
            bulk_cp(r_sm + STG_BYTES,     Rptr + KCH,     ROWBYTES, mbar + 8);
            bulk_cp(r_sm + 2 * STG_BYTES, Rptr + 2 * KCH, ROWBYTES, mbar + 16);
        }

        float acc[2][8][4];
        #pragma unroll
        for (int mt = 0; mt < 2; mt++)
            #pragma unroll
            for (int nt = 0; nt < 8; nt++)
                #pragma unroll
                for (int i = 0; i < 4; i++) acc[mt][nt][i] = 0.f;

        #pragma unroll 1
        for (int s = 0; s < NSTAGE; s++) {
            int b = s & (NRING - 1);
            mbar_wait(mbar + b * 8, ph[b]);
            ph[b] ^= 1;
            __syncthreads();               // all warps done with buffer (s-1)&3

            if (s + 3 < NSTAGE) {
                int nb = (s + 3) & (NRING - 1);   // just-freed buffer
                if (tid == 0) mbar_expect_tx(mbar + nb * 8, TX_BYTES);
                if (is_loader)
                    bulk_cp(r_sm + (uint32_t)nb * STG_BYTES, Rptr + (s + 3) * KCH,
                            ROWBYTES, mbar + nb * 8);
            }

            uint32_t stg = smb + (uint32_t)b * STG_BYTES;

            #pragma unroll
            for (int kk = 0; kk < KCH / 16; kk++) {
                uint32_t koff = (uint32_t)kk * 32u;
                uint32_t a[2][4], bfr[4][4];
                #pragma unroll
                for (int mt = 0; mt < 2; mt++)
                    ldsm4(a[mt][0], a[mt][1], a[mt][2], a[mt][3], stg + a_off[mt] + koff);
                #pragma unroll
                for (int nt2 = 0; nt2 < 4; nt2++)
                    ldsm4(bfr[nt2][0], bfr[nt2][1], bfr[nt2][2], bfr[nt2][3], stg + b_off[nt2] + koff);
                #pragma unroll
                for (int mt = 0; mt < 2; mt++)
                    #pragma unroll
                    for (int nt = 0; nt < 8; nt++)
                        mma_f16(acc[mt][nt], a[mt], bfr[nt >> 1][(nt & 1) * 2], bfr[nt >> 1][(nt & 1) * 2 + 1]);
            }
        }

        // ---------------- epilogue ----------------
        const float* brw = ((mode == 0) ? b1 : b2) + (size_t)e * D + n0;

        #pragma unroll
        for (int mt = 0; mt < 2; mt++) {
            #pragma unroll
            for (int rr = 0; rr < 2; rr++) {
                int m = m0 + wm + mt * 16 + rr * 8 + g;
                if (m >= ne) continue;
                size_t rowbase = ((size_t)e * CAP + m) * D + n0;
                #pragma unroll
                for (int nt = 0; nt < 8; nt++) {
                    int col = wn + nt * 8 + tg * 2;
                    float v0 = acc[mt][nt][rr * 2 + 0] + brw[col];
                    float v1 = acc[mt][nt][rr * 2 + 1] + brw[col + 1];
                    if (mode == 0) {
                        v0 = fmaxf(v0, 0.f);
                        v1 = fmaxf(v1, 0.f);
                        *(__half2*)(g_Hh + rowbase + col) = __floats2half2_rn(v0, v1);
                    } else {
                        *(float2*)(g_O + rowbase + col) = make_float2(v0, v1);
                    }
                }
            }
        }

        if (mode == 0) {
            __threadfence();            // H stores visible before readiness publish
            __syncthreads();
            if (tid == 0) atomicAdd(&g_ready[e * MT_TILES + mt_i], 1);
        }
    }
}

// ---------------- combine (float4) ----------------
__global__ void combine_kernel(float* __restrict__ y, int N)
{
    int token = blockIdx.x;
    if (token >= N) return;
    int   s0 = g_slot[token * 2 + 0];
    int   s1 = g_slot[token * 2 + 1];
    float w0 = g_wgt[token * 2 + 0];
    float w1 = g_wgt[token * 2 + 1];
    const float4* o0 = (const float4*)(g_O + (size_t)s0 * D);
    const float4* o1 = (const float4*)(g_O + (size_t)s1 * D);
    float4* yr = (float4*)(y + (size_t)token * D);
    for (int i = threadIdx.x; i < D / 4; i += blockDim.x) {
        float4 a = o0[i], b = o1[i];
        float4 r;
        r.x = w0 * a.x + w1 * b.x;
        r.y = w0 * a.y + w1 * b.y;
        r.z = w0 * a.z + w1 * b.z;
        r.w = w0 * a.w + w1 * b.w;
        yr[i] = r;
    }
}

extern "C" void kernel_launch(void* const* d_in, const int* in_sizes, int n_in,
                              void* d_out, int out_size)
{
    const float* x  = (const float*)d_in[0];
    const float* gW = (const float*)d_in[1];
    const float* gb = (const float*)d_in[2];
    const float* w1 = (const float*)d_in[3];
    const float* b1 = (const float*)d_in[4];
    const float* w2 = (const float*)d_in[5];
    const float* b2 = (const float*)d_in[6];

    int N = in_sizes[0] / D;   // 4096

    float* y         = (float*)d_out;
    float* gate_prob = (float*)d_out + (size_t)N * D;

    static int sm_count = 0;
    if (!sm_count) {
        cudaDeviceGetAttribute(&sm_count, cudaDevAttrMultiProcessorCount, 0);
        if (sm_count <= 0) sm_count = 148;
        cudaFuncSetAttribute(expert_gemm_persistent,
                             cudaFuncAttributeMaxDynamicSharedMemorySize, SMEM_BYTES);
    }

    zero_counts_kernel<<<1, 32>>>();
    convert_w_kernel<<<1184, 256>>>(w1, w2);
    gate_kernel<<<N, 256>>>(x, gW, gb, gate_prob, N);

    expert_gemm_persistent<<<sm_count, 512, SMEM_BYTES>>>(b1, b2);

    combine_kernel<<<N, 256>>>(y, N);
}

// round 16
// speedup vs baseline: 1.1862x; 1.0135x over previous
#include <cuda_runtime.h>
#include <cuda_fp16.h>
#include <math.h>
#include <stdint.h>

#define E 8
#define D 1024
#define NMAX 4096
#define CAP 4096

#define BM 128
#define BN 128
#define KCH 64                 // halfs of K per stage
#define NSTAGE (D / KCH)       // 16
#define NRING 3
#define ROWPAD 72              // halfs per smem row (144B)
#define ROWBYTES (KCH * 2)     // 128B payload per row per stage
#define STG_BYTES ((BM + BN) * ROWPAD * 2)     // 36864
#define TX_BYTES  ((BM + BN) * ROWBYTES)       // 32768 per stage
#define SMEM_BYTES (NRING * STG_BYTES)         // 110592

#define MT_TILES (NMAX / BM)       // 32
#define NT_TILES (D / BN)          // 8
#define TILES_PER_PASS (MT_TILES * E * NT_TILES)   // 2048
#define TOTAL_TILES (2 * TILES_PER_PASS)           // 4096

// ---------------- scratch (device globals; no runtime allocation) ----------------
__device__ __half g_Hh[(size_t)E * CAP * D];
__device__ float  g_O[(size_t)E * CAP * D];
__device__ __half g_xh[(size_t)NMAX * D];
__device__ __half g_W1h[(size_t)E * D * D];
__device__ __half g_W2h[(size_t)E * D * D];
__device__ int    g_cnt[E];
__device__ int    g_tok[E * CAP];
__device__ int    g_slot[NMAX * 2];
__device__ float  g_wgt[NMAX * 2];
__device__ int    g_tile_ctr;
__device__ int    g_ready[E * MT_TILES];

// ---------------- helpers ----------------
__device__ __forceinline__ uint32_t smem_u32(const void* p) {
    uint32_t a;
    asm("{ .reg .u64 t; cvta.to.shared.u64 t, %1; cvt.u32.u64 %0, t; }" : "=r"(a) : "l"(p));
    return a;
}
__device__ __forceinline__ void bulk_cp(uint32_t dst, const void* src, uint32_t bytes, uint32_t mbar) {
    asm volatile(
        "cp.async.bulk.shared::cta.global.mbarrier::complete_tx::bytes [%0], [%1], %2, [%3];"
        :: "r"(dst), "l"(src), "r"(bytes), "r"(mbar) : "memory");
}
__device__ __forceinline__ void mbar_init(uint32_t mbar, uint32_t count) {
    asm volatile("mbarrier.init.shared.b64 [%0], %1;" :: "r"(mbar), "r"(count) : "memory");
}
__device__ __forceinline__ void mbar_expect_tx(uint32_t mbar, uint32_t bytes) {
    asm volatile("mbarrier.arrive.expect_tx.shared.b64 _, [%0], %1;" :: "r"(mbar), "r"(bytes) : "memory");
}
__device__ __forceinline__ void mbar_wait(uint32_t mbar, uint32_t parity) {
    uint32_t done;
    asm volatile(
        "{\n\t.reg .pred p;\n\t"
        "mbarrier.try_wait.parity.shared.b64 p, [%1], %2;\n\t"
        "selp.b32 %0, 1, 0, p;\n\t}"
        : "=r"(done) : "r"(mbar), "r"(parity) : "memory");
    if (!done) {
        asm volatile(
            "{\n\t.reg .pred P1;\n\t"
            "WL_%=:\n\t"
            "mbarrier.try_wait.parity.shared.b64 P1, [%0], %1, 0x989680;\n\t"
            "@P1 bra.uni WD_%=;\n\t"
            "bra.uni WL_%=;\n\t"
            "WD_%=:\n\t}"
            :: "r"(mbar), "r"(parity) : "memory");
    }
}
__device__ __forceinline__ void ldsm4(uint32_t& r0, uint32_t& r1, uint32_t& r2, uint32_t& r3,
                                      uint32_t addr) {
    asm volatile("ldmatrix.sync.aligned.m8n8.x4.shared.b16 {%0,%1,%2,%3}, [%4];"
                 : "=r"(r0), "=r"(r1), "=r"(r2), "=r"(r3) : "r"(addr));
}
__device__ __forceinline__ void mma_f16(float* c, const uint32_t* a, uint32_t b0, uint32_t b1) {
    asm volatile(
        "mma.sync.aligned.m16n8k16.row.col.f32.f16.f16.f32 "
        "{%0,%1,%2,%3}, {%4,%5,%6,%7}, {%8,%9}, {%0,%1,%2,%3};"
        : "+f"(c[0]), "+f"(c[1]), "+f"(c[2]), "+f"(c[3])
        : "r"(a[0]), "r"(a[1]), "r"(a[2]), "r"(a[3]), "r"(b0), "r"(b1));
}

__global__ void zero_counts_kernel() {
    if (threadIdx.x < E) g_cnt[threadIdx.x] = 0;
    if (threadIdx.x == 0) g_tile_ctr = 0;
    for (int i = threadIdx.x; i < E * MT_TILES; i += 32) g_ready[i] = 0;
}

// ---------------- convert weights to fp16 ----------------
__global__ void convert_w_kernel(const float* __restrict__ w1,
                                 const float* __restrict__ w2)
{
    size_t n = (size_t)E * D * D / 4;
    size_t i = (size_t)blockIdx.x * blockDim.x + threadIdx.x;
    size_t stride = (size_t)gridDim.x * blockDim.x;
    for (; i < n; i += stride) {
        float4 v1 = ((const float4*)w1)[i];
        __half2* o1 = (__half2*)g_W1h + i * 2;
        o1[0] = __floats2half2_rn(v1.x, v1.y);
        o1[1] = __floats2half2_rn(v1.z, v1.w);
        float4 v2 = ((const float4*)w2)[i];
        __half2* o2 = (__half2*)g_W2h + i * 2;
        o2[0] = __floats2half2_rn(v2.x, v2.y);
        o2[1] = __floats2half2_rn(v2.z, v2.w);
    }
}

// ---------------- gating (emits fp16 x) ----------------
__global__ void gate_kernel(const float* __restrict__ x,
                            const float* __restrict__ gW,
                            const float* __restrict__ gb,
                            float* __restrict__ gate_prob_out,
                            int N)
{
    int token = blockIdx.x;
    if (token >= N) return;

    __shared__ float sx[D];
    __shared__ float slog[E];

    const float* xr = x + (size_t)token * D;
    __half* xout = g_xh + (size_t)token * D;
    for (int i = threadIdx.x; i < D; i += blockDim.x) {
        float v = xr[i];
        sx[i] = v;
        xout[i] = __float2half_rn(v);
    }
    __syncthreads();

    int w = threadIdx.x >> 5, lane = threadIdx.x & 31;
    float s = 0.f;
    const float* wr = gW + w * D;
    for (int k = lane; k < D; k += 32) s += sx[k] * wr[k];
    #pragma unroll
    for (int o = 16; o; o >>= 1) s += __shfl_xor_sync(0xffffffffu, s, o);
    if (lane == 0) slog[w] = s + gb[w];
    __syncthreads();

    if (threadIdx.x == 0) {
        float p[E];
        float mx = -1e30f;
        #pragma unroll
        for (int e = 0; e < E; e++) mx = fmaxf(mx, slog[e]);
        float sum = 0.f;
        #pragma unroll
        for (int e = 0; e < E; e++) { p[e] = expf(slog[e] - mx); sum += p[e]; }
        float inv = 1.f / sum;

        int i0 = 0; float p0 = -1.f;
        #pragma unroll
        for (int e = 0; e < E; e++) {
            p[e] *= inv;
            gate_prob_out[(size_t)token * E + e] = p[e];
            if (p[e] > p0) { p0 = p[e]; i0 = e; }
        }
        int i1 = -1; float p1 = -1.f;
        #pragma unroll
        for (int e = 0; e < E; e++)
            if (e != i0 && p[e] > p1) { p1 = p[e]; i1 = e; }

        float e1 = expf(p1 - p0);
        float w0 = 1.f / (1.f + e1);
        float w1 = e1 / (1.f + e1);

        int pos0 = atomicAdd(&g_cnt[i0], 1);
        int pos1 = atomicAdd(&g_cnt[i1], 1);
        g_tok[i0 * CAP + pos0] = token;
        g_tok[i1 * CAP + pos1] = token;
        g_slot[token * 2 + 0] = i0 * CAP + pos0;
        g_slot[token * 2 + 1] = i1 * CAP + pos1;
        g_wgt[token * 2 + 0] = w0;
        g_wgt[token * 2 + 1] = w1;
    }
}

// ---------------- persistent fused two-pass expert GEMM (2 CTAs/SM) ----------------
// 128x128 tile, 256 threads = 8 warps (4m x 2n, warp tile 32x64).
// Tile queue: ids [0, 2048) = pass 1, [2048, 4096) = pass 2.
__global__ __launch_bounds__(256, 2)
void expert_gemm_persistent(const float* __restrict__ b1,
                            const float* __restrict__ b2)
{
    extern __shared__ char sm[];
    __shared__ uint64_t mbar_store[NRING];
    __shared__ int s_tile;
    uint32_t smb  = smem_u32(sm);
    uint32_t mbar = smem_u32(mbar_store);

    int tid = threadIdx.x;   // 0..255
    int wid = tid >> 5, lane = tid & 31;
    int g  = lane >> 2, tg = lane & 3;
    int wm = (wid >> 1) * 32;       // 4 warps in m (32 rows each)
    int wn = (wid & 1) * 64;        // 2 warps in n (64 cols each)

    if (tid == 0)
        #pragma unroll
        for (int b = 0; b < NRING; b++) mbar_init(mbar + b * 8, 1);
    __syncthreads();

    // ldmatrix offsets (bytes within a stage) — tile-independent
    uint32_t a_off[2], b_off[4];
    #pragma unroll
    for (int mt = 0; mt < 2; mt++) {
        int row = wm + mt * 16 + (lane & 15);
        a_off[mt] = (uint32_t)(row * ROWPAD + (lane >> 4) * 8) * 2u;
    }
    #pragma unroll
    for (int nt2 = 0; nt2 < 4; nt2++) {
        int row = wn + nt2 * 16 + (lane & 7) + ((lane >> 4) & 1) * 8;
        b_off[nt2] = (uint32_t)((BM + row) * ROWPAD + ((lane >> 3) & 1) * 8) * 2u;
    }

    uint32_t r_sm = smb + (uint32_t)tid * (ROWPAD * 2);   // every thread owns a row

    int ph[NRING] = {0, 0, 0};

    for (;;) {
        if (tid == 0) s_tile = atomicAdd(&g_tile_ctr, 1);
        __syncthreads();
        int t = s_tile;
        __syncthreads();
        if (t >= TOTAL_TILES) break;

        int mode = (t >= TILES_PER_PASS) ? 1 : 0;
        int idx  = mode ? (t - TILES_PER_PASS) : t;
        int mt_i = idx >> 6;            // 64 = E * NT_TILES
        int e    = (idx >> 3) & 7;
        int nt_i = idx & 7;
        int ne   = g_cnt[e];
        int m0   = mt_i * BM;
        int n0   = nt_i * BN;
        if (m0 >= ne) continue;

        // pass-2: wait for this (e, m-tile) to be fully produced by pass-1
        if (mode == 1) {
            if (tid == 0) {
                const int* rp = &g_ready[e * MT_TILES + mt_i];
                int v;
                do {
                    asm volatile("ld.global.cg.s32 %0, [%1];" : "=r"(v) : "l"(rp) : "memory");
                } while (v < NT_TILES);
            }
            __syncthreads();
        }

        // per-tile loader pointer (every thread loads one row)
        const __half* Rptr;
        if (tid < BM) {
            if (mode == 0) {
                int tok = (m0 + tid < ne) ? g_tok[e * CAP + m0 + tid] : 0;
                Rptr = g_xh + (size_t)tok * D;
            } else {
                Rptr = g_Hh + ((size_t)e * CAP + m0 + tid) * D;
            }
        } else {
            const __half* W = (mode == 0) ? g_W1h : g_W2h;
            Rptr = W + ((size_t)e * D + n0 + (tid - BM)) * D;
        }

        // prologue: stages 0..1 into buffers 0..1
        if (tid == 0) {
            mbar_expect_tx(mbar + 0, TX_BYTES);
            mbar_expect_tx(mbar + 8, TX_BYTES);
        }
        __syncthreads();
        bulk_cp(r_sm,             Rptr,       ROWBYTES, mbar);
        bulk_cp(r_sm + STG_BYTES, Rptr + KCH, ROWBYTES, mbar + 8);

        float acc[2][8][4];
        #pragma unroll
        for (int mt = 0; mt < 2; mt++)
            #pragma unroll
            for (int nt = 0; nt < 8; nt++)
                #pragma unroll
                for (int i = 0; i < 4; i++) acc[mt][nt][i] = 0.f;

        #pragma unroll 1
        for (int s = 0; s < NSTAGE; s++) {
            int b = s % NRING;
            mbar_wait(mbar + b * 8, ph[b]);
            ph[b] ^= 1;
            __syncthreads();               // all warps done with buffer (s-1)%3

            if (s + 2 < NSTAGE) {
                int nb = (s + 2) % NRING;  // just-freed buffer
                if (tid == 0) mbar_expect_tx(mbar + nb * 8, TX_BYTES);
                bulk_cp(r_sm + (uint32_t)nb * STG_BYTES, Rptr + (s + 2) * KCH,
                        ROWBYTES, mbar + nb * 8);
            }

            uint32_t stg = smb + (uint32_t)b * STG_BYTES;

            #pragma unroll
            for (int kk = 0; kk < KCH / 16; kk++) {
                uint32_t koff = (uint32_t)kk * 32u;
                uint32_t a[2][4], bfr[4][4];
                #pragma unroll
                for (int mt = 0; mt < 2; mt++)
                    ldsm4(a[mt][0], a[mt][1], a[mt][2], a[mt][3], stg + a_off[mt] + koff);
                #pragma unroll
                for (int nt2 = 0; nt2 < 4; nt2++)
                    ldsm4(bfr[nt2][0], bfr[nt2][1], bfr[nt2][2], bfr[nt2][3], stg + b_off[nt2] + koff);
                #pragma unroll
                for (int mt = 0; mt < 2; mt++)
                    #pragma unroll
                    for (int nt = 0; nt < 8; nt++)
                        mma_f16(acc[mt][nt], a[mt], bfr[nt >> 1][(nt & 1) * 2], bfr[nt >> 1][(nt & 1) * 2 + 1]);
            }
        }

        // ---------------- epilogue ----------------
        const float* brw = ((mode == 0) ? b1 : b2) + (size_t)e * D + n0;

        #pragma unroll
        for (int mt = 0; mt < 2; mt++) {
            #pragma unroll
            for (int rr = 0; rr < 2; rr++) {
                int m = m0 + wm + mt * 16 + rr * 8 + g;
                if (m >= ne) continue;
                size_t rowbase = ((size_t)e * CAP + m) * D + n0;
                #pragma unroll
                for (int nt = 0; nt < 8; nt++) {
                    int col = wn + nt * 8 + tg * 2;
                    float v0 = acc[mt][nt][rr * 2 + 0] + brw[col];
                    float v1 = acc[mt][nt][rr * 2 + 1] + brw[col + 1];
                    if (mode == 0) {
                        v0 = fmaxf(v0, 0.f);
                        v1 = fmaxf(v1, 0.f);
                        *(__half2*)(g_Hh + rowbase + col) = __floats2half2_rn(v0, v1);
                    } else {
                        *(float2*)(g_O + rowbase + col) = make_float2(v0, v1);
                    }
                }
            }
        }

        if (mode == 0) {
            __threadfence();            // H stores visible before readiness publish
            __syncthreads();
            if (tid == 0) atomicAdd(&g_ready[e * MT_TILES + mt_i], 1);
        }
    }
}

// ---------------- combine (float4) ----------------
__global__ void combine_kernel(float* __restrict__ y, int N)
{
    int token = blockIdx.x;
    if (token >= N) return;
    int   s0 = g_slot[token * 2 + 0];
    int   s1 = g_slot[token * 2 + 1];
    float w0 = g_wgt[token * 2 + 0];
    float w1 = g_wgt[token * 2 + 1];
    const float4* o0 = (const float4*)(g_O + (size_t)s0 * D);
    const float4* o1 = (const float4*)(g_O + (size_t)s1 * D);
    float4* yr = (float4*)(y + (size_t)token * D);
    for (int i = threadIdx.x; i < D / 4; i += blockDim.x) {
        float4 a = o0[i], b = o1[i];
        float4 r;
        r.x = w0 * a.x + w1 * b.x;
        r.y = w0 * a.y + w1 * b.y;
        r.z = w0 * a.z + w1 * b.z;
        r.w = w0 * a.w + w1 * b.w;
        yr[i] = r;
    }
}

extern "C" void kernel_launch(void* const* d_in, const int* in_sizes, int n_in,
                              void* d_out, int out_size)
{
    const float* x  = (const float*)d_in[0];
    const float* gW = (const float*)d_in[1];
    const float* gb = (const float*)d_in[2];
    const float* w1 = (const float*)d_in[3];
    const float* b1 = (const float*)d_in[4];
    const float* w2 = (const float*)d_in[5];
    const float* b2 = (const float*)d_in[6];

    int N = in_sizes[0] / D;   // 4096

    float* y         = (float*)d_out;
    float* gate_prob = (float*)d_out + (size_t)N * D;

    static int sm_count = 0;
    if (!sm_count) {
        cudaDeviceGetAttribute(&sm_count, cudaDevAttrMultiProcessorCount, 0);
        if (sm_count <= 0) sm_count = 148;
        cudaFuncSetAttribute(expert_gemm_persistent,
                             cudaFuncAttributeMaxDynamicSharedMemorySize, SMEM_BYTES);
    }

    zero_counts_kernel<<<1, 32>>>();
    convert_w_kernel<<<1184, 256>>>(w1, w2);
    gate_kernel<<<N, 256>>>(x, gW, gb, gate_prob, N);

    expert_gemm_persistent<<<2 * sm_count, 256, SMEM_BYTES>>>(b1, b2);

    combine_kernel<<<N, 256>>>(y, N);
}